// round 15
// baseline (speedup 1.0000x reference)
#include <cuda_runtime.h>

// Problem dims (fixed)
#define BB   512
#define TT   100
#define II   700
#define HH   128
#define OO   20
#define NROWS (BB*TT)
#define MW   24                    // padded mask words per row (22 used + 2 zero)
#define CHUNK_I 192                // i-rows per weight chunk
#define CHUNK_W 6                  // mask words per chunk
#define NCHUNK 4
#define GW_ROWS 11                 // rows per warp in single-pass gather
#define TRANS_BLOCKS 350           // CTAs of fused kernel doing the transpose

#define ALPHA 0.81873075307798182f // exp(-0.2)
#define BETA  0.90483741803595957f // exp(-0.1)
#define LAM   0.95122942450071400f // exp(-0.05)

// Device-global scratch (allocation-free)
static __device__ float    g_W0T[II * HH];               // W0^T [i][h]
static __device__ unsigned g_masks[(size_t)NROWS * MW];  // input spike bitmasks (sequential)
static __device__ float    g_U[(size_t)NROWS * HH];      // U = X @ W0^T
static __device__ float    g_G[(size_t)NROWS * HH];      // G = k0 @ W1^T

// ---------------------------------------------------------------------------
// K0 (launch 0): FUSED transpose + input-bitmask extraction (MLP-6 loads,
// sequential bit order: word w bit j <-> element 32w+j).
// ---------------------------------------------------------------------------
__global__ void __launch_bounds__(256) k_fused_tm(const float* __restrict__ W0,
                                                  const float* __restrict__ X) {
    if (blockIdx.x < TRANS_BLOCKS) {
        int idx = blockIdx.x * 256 + threadIdx.x;   // covers II*HH = 89600 exactly
        int i = idx >> 7, h = idx & 127;
        g_W0T[idx] = W0[h * II + i];
        return;
    }
    int warp = ((blockIdx.x - TRANS_BLOCKS) * 256 + threadIdx.x) >> 5;
    int lane = threadIdx.x & 31;
    if (warp >= NROWS) return;
    const float4* xr4 = (const float4*)(X + (size_t)warp * II);

    float4 v[6];
    #pragma unroll
    for (int k = 0; k < 6; k++) {
        v[k] = make_float4(0.f, 0.f, 0.f, 0.f);
        if (k < 5 || lane < 15)
            v[k] = __ldg(xr4 + k * 32 + lane);
    }

    unsigned mw = 0;
    int myk = lane >> 2;
    int myg = lane & 3;
    #pragma unroll
    for (int k = 0; k < 6; k++) {
        unsigned nib = (v[k].x != 0.f ? 1u : 0u) | (v[k].y != 0.f ? 2u : 0u)
                     | (v[k].z != 0.f ? 4u : 0u) | (v[k].w != 0.f ? 8u : 0u);
        unsigned part = nib << ((lane & 7) * 4);
        part |= __shfl_xor_sync(0xffffffffu, part, 1);
        part |= __shfl_xor_sync(0xffffffffu, part, 2);
        part |= __shfl_xor_sync(0xffffffffu, part, 4);
        unsigned wd = __shfl_sync(0xffffffffu, part, myg * 8);
        if (k == myk) mw = wd;
    }
    if (lane < MW) g_masks[(size_t)warp * MW + lane] = mw;
}

// ---------------------------------------------------------------------------
// K1 (launch 1): SINGLE-PASS U gather, register accumulators, scalar ffs
// decode (input spikes ~10% dense -> sparse iteration is right here).
// ---------------------------------------------------------------------------
__global__ void __launch_bounds__(256, 2) k_gather() {
    extern __shared__ float4 Ws4[];            // [192][32] float4
    int warp = threadIdx.x >> 5, lane = threadIdx.x & 31;
    int gw = blockIdx.x * 8 + warp;
    int r0 = gw * GW_ROWS;

    unsigned mw[GW_ROWS];
    #pragma unroll
    for (int k = 0; k < GW_ROWS; k++) {
        int row = r0 + k;
        mw[k] = (row < NROWS && lane < MW)
              ? g_masks[(size_t)row * MW + lane] : 0u;
    }

    float4 acc[GW_ROWS];
    #pragma unroll
    for (int k = 0; k < GW_ROWS; k++)
        acc[k] = make_float4(0.f, 0.f, 0.f, 0.f);

    for (int c = 0; c < NCHUNK; c++) {
        __syncthreads();
        for (int idx = threadIdx.x; idx < CHUNK_I * 32; idx += 256) {
            int i = idx >> 5, q = idx & 31;
            int gi = c * CHUNK_I + i;
            float4 v = make_float4(0.f, 0.f, 0.f, 0.f);
            if (gi < II) v = *(const float4*)(g_W0T + gi * HH + q * 4);
            Ws4[idx] = v;
        }
        __syncthreads();

        #pragma unroll
        for (int k = 0; k < GW_ROWS; k++) {
            #pragma unroll
            for (int w = 0; w < CHUNK_W; w++) {
                unsigned m = __shfl_sync(0xffffffffu, mw[k], c * CHUNK_W + w);
                const float4* p = Ws4 + w * 32 * 32 + lane;
                while (m) {
                    int j = __ffs(m) - 1;
                    m &= m - 1;
                    float4 v = p[j * 32];
                    acc[k].x += v.x; acc[k].y += v.y;
                    acc[k].z += v.z; acc[k].w += v.w;
                }
            }
        }
    }

    #pragma unroll
    for (int k = 0; k < GW_ROWS; k++) {
        int row = r0 + k;
        if (row < NROWS)
            ((float4*)(g_U + (size_t)row * HH))[lane] = acc[k];
    }
}

// ---------------------------------------------------------------------------
// K2 (launch 2): FUSED layer-0 scan + G gather (k0 spikes sparse -> ffs).
// ---------------------------------------------------------------------------
__global__ void __launch_bounds__(256, 2) k_layer0G(const float* __restrict__ W1) {
    extern __shared__ float sm2[];
    float* W1s = sm2;                               // [128][128]  64 KB
    unsigned* k0m = (unsigned*)(W1s + HH * HH);     // [2][TT][4]  3.2 KB

    for (int idx = threadIdx.x; idx < HH * HH; idx += 256) {
        int h = idx >> 7, j = idx & 127;
        W1s[j * 128 + h] = W1[idx];
    }
    __syncthreads();

    int w = threadIdx.x >> 5;
    int lane = threadIdx.x & 31;

    // ---- Phase A: LIF scan (prefetch depth 4) ----
    {
        int s = w >> 2, c = w & 3;                  // sample-in-CTA, chunk
        int b = blockIdx.x * 2 + s;
        const float* Ub = g_U + (size_t)b * TT * HH + c * 32 + lane;
        unsigned* K0s = k0m + s * TT * 4 + c;

        float s0 = 0.f, m0 = 0.f;
        float buf[4];
        #pragma unroll
        for (int r = 0; r < 4; r++) buf[r] = Ub[(size_t)r * HH];

        for (int t0 = 0; t0 < TT; t0 += 4) {
            float nxt[4];
            #pragma unroll
            for (int r = 0; r < 4; r++) {
                int tn = t0 + 4 + r;
                nxt[r] = (tn < TT) ? Ub[(size_t)tn * HH] : 0.f;
            }
            #pragma unroll
            for (int r = 0; r < 4; r++) {
                s0 = ALPHA * s0 + buf[r];
                m0 = BETA * m0 + s0;
                bool sp = m0 > 1.0f;
                if (sp) m0 = 0.f;
                unsigned bm = __ballot_sync(0xffffffffu, sp);
                if (lane == 0) K0s[(t0 + r) * 4] = bm;
            }
            #pragma unroll
            for (int r = 0; r < 4; r++) buf[r] = nxt[r];
        }
    }
    __syncthreads();

    // ---- Phase B: G gather (2*TT rows per CTA, warp per row) ----
    const float4* W1s4 = (const float4*)W1s;        // [j][32] float4
    for (int r = w; r < 2 * TT; r += 8) {
        int s2 = (r >= TT) ? 1 : 0;
        int t = r - s2 * TT;
        int b2 = blockIdx.x * 2 + s2;
        unsigned mw = (lane < 4) ? k0m[s2 * TT * 4 + t * 4 + lane] : 0u;
        float4 acc = make_float4(0.f, 0.f, 0.f, 0.f);
        #pragma unroll
        for (int q = 0; q < 4; q++) {
            unsigned m = __shfl_sync(0xffffffffu, mw, q);
            const float4* p = W1s4 + q * 32 * 32 + lane;
            while (m) {
                int j = __ffs(m) - 1;
                m &= m - 1;
                float4 v = p[j * 32];
                acc.x += v.x; acc.y += v.y; acc.z += v.z; acc.w += v.w;
            }
        }
        *(float4*)(g_G + ((size_t)b2 * TT + t) * HH + lane * 4) = acc;
    }
}

// ---------------------------------------------------------------------------
// K3 (launch 3 — profiled): layer-1 recurrence, FLOAT2-PAIRED dense gather.
// Thread owns neurons {c, c+64} (c = tid & 63); sample = 64 threads =
// 2 warps; 4 samples/CTA (256 thr), grid 128.
// Per j: 1 LDS.64 + 1 bit-test + 2 predicated FADDs = 4 instr / 2 neurons
// (per-neuron float addition sequence ascending j -> bit-identical to R12).
// Masks: 2 ballots/warp -> SMEM -> 64-thr named barrier per sample.
// ---------------------------------------------------------------------------
__global__ void __launch_bounds__(256, 1) k_layer1(
    const float* __restrict__ V1, const float* __restrict__ Wr,
    const float* __restrict__ br, float* __restrict__ out)
{
    extern __shared__ float sm6[];
    float2* V1s2 = (float2*)sm6;                    // [128 j][64 c]  64 KB
    float*  Wrs  = (float*)(V1s2 + HH * 64);        // 128*20  10 KB
    float*  brs  = Wrs + HH * OO;                   // 32
    unsigned* km = (unsigned*)(brs + 32);           // [4 samples][4] current masks
    uint4*  hist = (uint4*)(km + 16);               // [4 samples][100]  6.4 KB

    // Fill V1s2: coalesced V1 reads, scattered SMEM writes.
    // V1s2[j][c] = { V1[c][j], V1[c+64][j] }
    for (int idx = threadIdx.x; idx < HH * HH; idx += 256) {
        int h = idx >> 7, j = idx & 127;      // coalesced read of V1[h][j]
        float v = V1[idx];
        int c = h & 63;
        float* dst = (float*)(V1s2 + j * 64 + c);
        dst[h >> 6] = v;                      // .x for h<64, .y for h>=64
    }
    for (int idx = threadIdx.x; idx < OO * HH; idx += 256) {
        int o = idx >> 7, j = idx & 127;
        Wrs[j * OO + o] = Wr[idx];
    }
    if (threadIdx.x < OO) brs[threadIdx.x] = br[threadIdx.x];
    __syncthreads();

    int g    = threadIdx.x >> 6;     // sample in CTA (0..3)
    int c    = threadIdx.x & 63;     // column: neurons c and c+64
    int wing = (threadIdx.x >> 5) & 1; // warp within sample: 0 = cols 0..31
    int lane = threadIdx.x & 31;
    int b    = blockIdx.x * 4 + g;
    unsigned* kg = km + g * 4;
    uint4* hw = hist + g * TT;
    int barid = g + 1;

    const float* Gb = g_G + (size_t)b * TT * HH;
    float* outb = out + (size_t)b * TT * OO;
    const float2* Vp = V1s2 + c;     // source j at Vp[j*64]

    float s1lo = 0.f, s1hi = 0.f, m1lo = 0.f, m1hi = 0.f;
    unsigned p0 = 0, p1 = 0, p2 = 0, p3 = 0;
    float gvLo = Gb[c],        gvHi = Gb[c + 64];
    float g1Lo = Gb[HH + c],   g1Hi = Gb[HH + c + 64];

    for (int t = 0; t < TT; t++) {
        float g2Lo = 0.f, g2Hi = 0.f;
        if (t + 2 < TT) {
            g2Lo = Gb[(size_t)(t + 2) * HH + c];
            g2Hi = Gb[(size_t)(t + 2) * HH + c + 64];
        }

        // Dense paired gather, ascending j (bit-exact per neuron).
        float aLo = 0.f, aHi = 0.f;
        #pragma unroll
        for (int jj = 0; jj < 32; jj++) {
            float2 v = Vp[jj * 64];
            if (p0 & (1u << jj)) { aLo += v.x; aHi += v.y; }
        }
        #pragma unroll
        for (int jj = 0; jj < 32; jj++) {
            float2 v = Vp[(32 + jj) * 64];
            if (p1 & (1u << jj)) { aLo += v.x; aHi += v.y; }
        }
        #pragma unroll
        for (int jj = 0; jj < 32; jj++) {
            float2 v = Vp[(64 + jj) * 64];
            if (p2 & (1u << jj)) { aLo += v.x; aHi += v.y; }
        }
        #pragma unroll
        for (int jj = 0; jj < 32; jj++) {
            float2 v = Vp[(96 + jj) * 64];
            if (p3 & (1u << jj)) { aLo += v.x; aHi += v.y; }
        }

        // LIF for both neurons (scalar, exact semantics).
        s1lo = (ALPHA * s1lo + gvLo) + aLo;
        m1lo = BETA * m1lo + s1lo;
        bool spLo = m1lo > 1.0f;
        if (spLo) m1lo = 0.f;

        s1hi = (ALPHA * s1hi + gvHi) + aHi;
        m1hi = BETA * m1hi + s1hi;
        bool spHi = m1hi > 1.0f;
        if (spHi) m1hi = 0.f;

        // Mask exchange: warp `wing` contributes words wing (lo) and 2+wing (hi).
        unsigned bmLo = __ballot_sync(0xffffffffu, spLo);
        unsigned bmHi = __ballot_sync(0xffffffffu, spHi);
        if (lane == 0) {
            kg[wing] = bmLo;         // neurons [wing*32, wing*32+32)
            kg[2 + wing] = bmHi;     // neurons [64+wing*32, ...)
        }
        asm volatile("bar.sync %0, %1;" :: "r"(barid), "r"(64) : "memory");
        p0 = kg[0]; p1 = kg[1]; p2 = kg[2]; p3 = kg[3];
        if (c == 0) hw[t] = make_uint4(p0, p1, p2, p3);

        gvLo = g1Lo; gvHi = g1Hi; g1Lo = g2Lo; g1Hi = g2Hi;
    }
    asm volatile("bar.sync %0, %1;" :: "r"(barid), "r"(64) : "memory");

    // Post-loop: threads c<20 (first warp of sample) do readout gather
    // (ascending j, sparse) + leaky scan — identical arithmetic order.
    if (c < OO) {
        const float C = 1.0f - LAM;
        float brv = brs[c];
        float rp = 0.f;
        for (int t = 0; t < TT; t++) {
            uint4 ms = hw[t];
            float racc = brv;
            unsigned m;
            m = ms.x; while (m) { int j = __ffs(m) - 1; m &= m - 1; racc += Wrs[j * OO + c]; }
            m = ms.y; while (m) { int j = __ffs(m) - 1; m &= m - 1; racc += Wrs[(32 + j) * OO + c]; }
            m = ms.z; while (m) { int j = __ffs(m) - 1; m &= m - 1; racc += Wrs[(64 + j) * OO + c]; }
            m = ms.w; while (m) { int j = __ffs(m) - 1; m &= m - 1; racc += Wrs[(96 + j) * OO + c]; }
            rp = LAM * rp + C * racc;
            outb[(size_t)t * OO + c] = rp;
        }
    }
}

// ---------------------------------------------------------------------------
// Launch
// ---------------------------------------------------------------------------
extern "C" void kernel_launch(void* const* d_in, const int* in_sizes, int n_in,
                              void* d_out, int out_size) {
    (void)in_sizes; (void)n_in; (void)out_size;
    const float* X  = (const float*)d_in[0];
    const float* W0 = (const float*)d_in[1];
    const float* W1 = (const float*)d_in[2];
    const float* V1 = (const float*)d_in[3];
    const float* Wr = (const float*)d_in[4];
    const float* br = (const float*)d_in[5];
    float* out = (float*)d_out;

    k_fused_tm<<<TRANS_BLOCKS + (NROWS + 7) / 8, 256>>>(W0, X);

    const size_t smem_g = (size_t)CHUNK_I * 32 * sizeof(float4);  // 98,304 B
    cudaFuncSetAttribute(k_gather, cudaFuncAttributeMaxDynamicSharedMemorySize,
                         (int)smem_g);
    int n_gw = (NROWS + GW_ROWS - 1) / GW_ROWS;
    k_gather<<<(n_gw + 7) / 8, 256, smem_g>>>();

    const size_t smem_0g = (size_t)HH * HH * sizeof(float)
                         + (size_t)2 * TT * 4 * sizeof(unsigned); // ~67.3 KB
    cudaFuncSetAttribute(k_layer0G, cudaFuncAttributeMaxDynamicSharedMemorySize,
                         (int)smem_0g);
    k_layer0G<<<BB / 2, 256, smem_0g>>>(W1);

    const size_t smem_l1 = (size_t)HH * 64 * sizeof(float2)       // V1s2 64 KB
                         + (size_t)(HH * OO + 32) * sizeof(float) // Wrs + brs
                         + 16 * sizeof(unsigned)                  // km
                         + (size_t)4 * TT * sizeof(uint4);        // hist 6.4 KB
    cudaFuncSetAttribute(k_layer1, cudaFuncAttributeMaxDynamicSharedMemorySize,
                         (int)smem_l1);
    k_layer1<<<BB / 4, 256, smem_l1>>>(V1, Wr, br, out);
}

// round 16
// speedup vs baseline: 1.7051x; 1.7051x over previous
#include <cuda_runtime.h>

// Problem dims (fixed)
#define BB   512
#define TT   100
#define II   700
#define HH   128
#define OO   20
#define NROWS (BB*TT)
#define MW   24                    // padded mask words per row (22 used + 2 zero)
#define CHUNK_I 192                // i-rows per weight chunk
#define CHUNK_W 6                  // mask words per chunk
#define NCHUNK 4
#define GW_ROWS 11                 // rows per warp in single-pass gather
#define TRANS_BLOCKS 350           // CTAs of fused kernel doing the transpose
#define NREG_J 96                  // V1 columns held in registers per thread

#define ALPHA 0.81873075307798182f // exp(-0.2)
#define BETA  0.90483741803595957f // exp(-0.1)
#define LAM   0.95122942450071400f // exp(-0.05)

// Device-global scratch (allocation-free)
static __device__ float    g_W0T[II * HH];               // W0^T [i][h]
static __device__ unsigned g_masks[(size_t)NROWS * MW];  // input spike bitmasks (sequential)
static __device__ float    g_U[(size_t)NROWS * HH];      // U = X @ W0^T
static __device__ float    g_G[(size_t)NROWS * HH];      // G = k0 @ W1^T

// ---------------------------------------------------------------------------
// K0 (launch 0): FUSED transpose + input-bitmask extraction (MLP-6 loads,
// sequential bit order: word w bit j <-> element 32w+j).
// ---------------------------------------------------------------------------
__global__ void __launch_bounds__(256) k_fused_tm(const float* __restrict__ W0,
                                                  const float* __restrict__ X) {
    if (blockIdx.x < TRANS_BLOCKS) {
        int idx = blockIdx.x * 256 + threadIdx.x;   // covers II*HH = 89600 exactly
        int i = idx >> 7, h = idx & 127;
        g_W0T[idx] = W0[h * II + i];
        return;
    }
    int warp = ((blockIdx.x - TRANS_BLOCKS) * 256 + threadIdx.x) >> 5;
    int lane = threadIdx.x & 31;
    if (warp >= NROWS) return;
    const float4* xr4 = (const float4*)(X + (size_t)warp * II);

    float4 v[6];
    #pragma unroll
    for (int k = 0; k < 6; k++) {
        v[k] = make_float4(0.f, 0.f, 0.f, 0.f);
        if (k < 5 || lane < 15)
            v[k] = __ldg(xr4 + k * 32 + lane);
    }

    unsigned mw = 0;
    int myk = lane >> 2;
    int myg = lane & 3;
    #pragma unroll
    for (int k = 0; k < 6; k++) {
        unsigned nib = (v[k].x != 0.f ? 1u : 0u) | (v[k].y != 0.f ? 2u : 0u)
                     | (v[k].z != 0.f ? 4u : 0u) | (v[k].w != 0.f ? 8u : 0u);
        unsigned part = nib << ((lane & 7) * 4);
        part |= __shfl_xor_sync(0xffffffffu, part, 1);
        part |= __shfl_xor_sync(0xffffffffu, part, 2);
        part |= __shfl_xor_sync(0xffffffffu, part, 4);
        unsigned wd = __shfl_sync(0xffffffffu, part, myg * 8);
        if (k == myk) mw = wd;
    }
    if (lane < MW) g_masks[(size_t)warp * MW + lane] = mw;
}

// ---------------------------------------------------------------------------
// K1 (launch 1): SINGLE-PASS U gather, register accumulators, scalar ffs
// decode (input spikes ~10% dense -> sparse iteration is right here).
// ---------------------------------------------------------------------------
__global__ void __launch_bounds__(256, 2) k_gather() {
    extern __shared__ float4 Ws4[];            // [192][32] float4
    int warp = threadIdx.x >> 5, lane = threadIdx.x & 31;
    int gw = blockIdx.x * 8 + warp;
    int r0 = gw * GW_ROWS;

    unsigned mw[GW_ROWS];
    #pragma unroll
    for (int k = 0; k < GW_ROWS; k++) {
        int row = r0 + k;
        mw[k] = (row < NROWS && lane < MW)
              ? g_masks[(size_t)row * MW + lane] : 0u;
    }

    float4 acc[GW_ROWS];
    #pragma unroll
    for (int k = 0; k < GW_ROWS; k++)
        acc[k] = make_float4(0.f, 0.f, 0.f, 0.f);

    for (int c = 0; c < NCHUNK; c++) {
        __syncthreads();
        for (int idx = threadIdx.x; idx < CHUNK_I * 32; idx += 256) {
            int i = idx >> 5, q = idx & 31;
            int gi = c * CHUNK_I + i;
            float4 v = make_float4(0.f, 0.f, 0.f, 0.f);
            if (gi < II) v = *(const float4*)(g_W0T + gi * HH + q * 4);
            Ws4[idx] = v;
        }
        __syncthreads();

        #pragma unroll
        for (int k = 0; k < GW_ROWS; k++) {
            #pragma unroll
            for (int w = 0; w < CHUNK_W; w++) {
                unsigned m = __shfl_sync(0xffffffffu, mw[k], c * CHUNK_W + w);
                const float4* p = Ws4 + w * 32 * 32 + lane;
                while (m) {
                    int j = __ffs(m) - 1;
                    m &= m - 1;
                    float4 v = p[j * 32];
                    acc[k].x += v.x; acc[k].y += v.y;
                    acc[k].z += v.z; acc[k].w += v.w;
                }
            }
        }
    }

    #pragma unroll
    for (int k = 0; k < GW_ROWS; k++) {
        int row = r0 + k;
        if (row < NROWS)
            ((float4*)(g_U + (size_t)row * HH))[lane] = acc[k];
    }
}

// ---------------------------------------------------------------------------
// K2 (launch 2): FUSED layer-0 scan + G gather (k0 spikes sparse -> ffs).
// ---------------------------------------------------------------------------
__global__ void __launch_bounds__(256, 2) k_layer0G(const float* __restrict__ W1) {
    extern __shared__ float sm2[];
    float* W1s = sm2;                               // [128][128]  64 KB
    unsigned* k0m = (unsigned*)(W1s + HH * HH);     // [2][TT][4]  3.2 KB

    for (int idx = threadIdx.x; idx < HH * HH; idx += 256) {
        int h = idx >> 7, j = idx & 127;
        W1s[j * 128 + h] = W1[idx];
    }
    __syncthreads();

    int w = threadIdx.x >> 5;
    int lane = threadIdx.x & 31;

    // ---- Phase A: LIF scan (prefetch depth 4) ----
    {
        int s = w >> 2, c = w & 3;                  // sample-in-CTA, chunk
        int b = blockIdx.x * 2 + s;
        const float* Ub = g_U + (size_t)b * TT * HH + c * 32 + lane;
        unsigned* K0s = k0m + s * TT * 4 + c;

        float s0 = 0.f, m0 = 0.f;
        float buf[4];
        #pragma unroll
        for (int r = 0; r < 4; r++) buf[r] = Ub[(size_t)r * HH];

        for (int t0 = 0; t0 < TT; t0 += 4) {
            float nxt[4];
            #pragma unroll
            for (int r = 0; r < 4; r++) {
                int tn = t0 + 4 + r;
                nxt[r] = (tn < TT) ? Ub[(size_t)tn * HH] : 0.f;
            }
            #pragma unroll
            for (int r = 0; r < 4; r++) {
                s0 = ALPHA * s0 + buf[r];
                m0 = BETA * m0 + s0;
                bool sp = m0 > 1.0f;
                if (sp) m0 = 0.f;
                unsigned bm = __ballot_sync(0xffffffffu, sp);
                if (lane == 0) K0s[(t0 + r) * 4] = bm;
            }
            #pragma unroll
            for (int r = 0; r < 4; r++) buf[r] = nxt[r];
        }
    }
    __syncthreads();

    // ---- Phase B: G gather (2*TT rows per CTA, warp per row) ----
    const float4* W1s4 = (const float4*)W1s;        // [j][32] float4
    for (int r = w; r < 2 * TT; r += 8) {
        int s2 = (r >= TT) ? 1 : 0;
        int t = r - s2 * TT;
        int b2 = blockIdx.x * 2 + s2;
        unsigned mw = (lane < 4) ? k0m[s2 * TT * 4 + t * 4 + lane] : 0u;
        float4 acc = make_float4(0.f, 0.f, 0.f, 0.f);
        #pragma unroll
        for (int q = 0; q < 4; q++) {
            unsigned m = __shfl_sync(0xffffffffu, mw, q);
            const float4* p = W1s4 + q * 32 * 32 + lane;
            while (m) {
                int j = __ffs(m) - 1;
                m &= m - 1;
                float4 v = p[j * 32];
                acc.x += v.x; acc.y += v.y; acc.z += v.z; acc.w += v.w;
            }
        }
        *(float4*)(g_G + ((size_t)b2 * TT + t) * HH + lane * 4) = acc;
    }
}

// ---------------------------------------------------------------------------
// K3 (launch 3 — profiled): layer-1 recurrence with V1 ROWS IN REGISTERS.
// Thread h holds V1[h][0..95] in 96 regs; j in [96,128) stays in SMEM
// (16 KB). Dense predicated gather: j<96 -> bit-test + predicated FADD
// (NO LDS); j>=96 -> LDS + test + FADD. Single ascending-j addition chain
// -> bit-identical to R12. Crossbar traffic per step: 2048 -> 512 cyc/SM.
// 2 samples/CTA (256 thr), 2 CTAs/SM = 16 warps/SM (reg-budget 128).
// ---------------------------------------------------------------------------
__global__ void __launch_bounds__(256, 2) k_layer1(
    const float* __restrict__ V1, const float* __restrict__ Wr,
    const float* __restrict__ br, float* __restrict__ out)
{
    extern __shared__ float sm6[];
    float* V1hi = sm6;                              // [32 j][128 h]  16 KB (j=96..127)
    float* Wrs  = V1hi + 32 * HH;                   // 128*20   10 KB
    float* brs  = Wrs + HH * OO;                    // 32
    float* ybuf = brs + 32;                         // 2*100*20 16 KB
    unsigned* hist = (unsigned*)(ybuf + 2 * TT * OO); // [2][TT][4] 3.2 KB

    // Fill V1hi[jj*128 + h] = V1[h][96+jj]
    for (int idx = threadIdx.x; idx < 32 * HH; idx += 256) {
        int hh = idx >> 5, jj = idx & 31;
        V1hi[jj * HH + hh] = V1[hh * HH + 96 + jj];
    }
    for (int idx = threadIdx.x; idx < OO * HH; idx += 256) {
        int o = idx >> 7, j = idx & 127;
        Wrs[j * OO + o] = Wr[idx];
    }
    if (threadIdx.x < OO) brs[threadIdx.x] = br[threadIdx.x];
    __syncthreads();

    int g    = threadIdx.x >> 7;     // sample in CTA
    int h    = threadIdx.x & 127;    // neuron
    int word = h >> 5;
    int lane = threadIdx.x & 31;
    int b    = blockIdx.x * 2 + g;
    unsigned* hg = hist + g * TT * 4;
    float* yg = ybuf + g * TT * OO;
    int barid = g + 1;

    // V1 row h, columns 0..95, in registers (one-time coalesced-ish fill).
    float vr[NREG_J];
    {
        const float4* Vrow = (const float4*)(V1 + (size_t)h * HH);
        #pragma unroll
        for (int q = 0; q < NREG_J / 4; q++) {
            float4 v = __ldg(Vrow + q);
            vr[q * 4 + 0] = v.x; vr[q * 4 + 1] = v.y;
            vr[q * 4 + 2] = v.z; vr[q * 4 + 3] = v.w;
        }
    }

    const float* Gb = g_G + (size_t)b * TT * HH;
    float* outb = out + (size_t)b * TT * OO;
    const float* Vhi = V1hi + h;     // SMEM source: col 96+jj at Vhi[jj*128]

    float s1 = 0.f, m1 = 0.f;
    unsigned p0 = 0, p1 = 0, p2 = 0, p3 = 0;
    float gv = Gb[h];

    for (int t = 0; t < TT; t++) {
        float gn = (t + 1 < TT) ? Gb[(size_t)(t + 1) * HH + h] : 0.f;

        // Dense predicated gather, ascending j (bit-exact vs R12).
        float acc = 0.f;
        #pragma unroll
        for (int jj = 0; jj < 32; jj++)
            if (p0 & (1u << jj)) acc += vr[jj];
        #pragma unroll
        for (int jj = 0; jj < 32; jj++)
            if (p1 & (1u << jj)) acc += vr[32 + jj];
        #pragma unroll
        for (int jj = 0; jj < 32; jj++)
            if (p2 & (1u << jj)) acc += vr[64 + jj];
        #pragma unroll
        for (int jj = 0; jj < 32; jj++) {
            float v = Vhi[jj * HH];
            if (p3 & (1u << jj)) acc += v;
        }

        s1 = (ALPHA * s1 + gv) + acc;
        m1 = BETA * m1 + s1;
        bool sp = m1 > 1.0f;
        if (sp) m1 = 0.f;

        unsigned bm = __ballot_sync(0xffffffffu, sp);
        if (lane == 0) hg[t * 4 + word] = bm;
        asm volatile("bar.sync %0, %1;" :: "r"(barid), "r"(128) : "memory");
        p0 = hg[t * 4 + 0]; p1 = hg[t * 4 + 1];
        p2 = hg[t * 4 + 2]; p3 = hg[t * 4 + 3];
        gv = gn;
    }

    // Post-loop readout: 2000 (t,o) tasks over the group's 128 threads
    // (identical arithmetic order to R12).
    for (int task = h; task < TT * OO; task += HH) {
        int t = task / OO, o = task - t * OO;
        float racc = brs[o];
        #pragma unroll
        for (int q = 0; q < 4; q++) {
            unsigned m = hg[t * 4 + q];
            const float* p = Wrs + q * 32 * OO + o;
            while (m) {
                int j = __ffs(m) - 1;
                m &= m - 1;
                racc += p[j * OO];
            }
        }
        yg[t * OO + o] = racc;
    }
    asm volatile("bar.sync %0, %1;" :: "r"(barid), "r"(128) : "memory");

    // Leaky scan per output channel (threads h < 20), identical rp chain.
    if (h < OO) {
        const float C = 1.0f - LAM;
        float rp = 0.f;
        for (int t = 0; t < TT; t++) {
            rp = LAM * rp + C * yg[t * OO + h];
            outb[(size_t)t * OO + h] = rp;
        }
    }
}

// ---------------------------------------------------------------------------
// Launch
// ---------------------------------------------------------------------------
extern "C" void kernel_launch(void* const* d_in, const int* in_sizes, int n_in,
                              void* d_out, int out_size) {
    (void)in_sizes; (void)n_in; (void)out_size;
    const float* X  = (const float*)d_in[0];
    const float* W0 = (const float*)d_in[1];
    const float* W1 = (const float*)d_in[2];
    const float* V1 = (const float*)d_in[3];
    const float* Wr = (const float*)d_in[4];
    const float* br = (const float*)d_in[5];
    float* out = (float*)d_out;

    k_fused_tm<<<TRANS_BLOCKS + (NROWS + 7) / 8, 256>>>(W0, X);

    const size_t smem_g = (size_t)CHUNK_I * 32 * sizeof(float4);  // 98,304 B
    cudaFuncSetAttribute(k_gather, cudaFuncAttributeMaxDynamicSharedMemorySize,
                         (int)smem_g);
    int n_gw = (NROWS + GW_ROWS - 1) / GW_ROWS;
    k_gather<<<(n_gw + 7) / 8, 256, smem_g>>>();

    const size_t smem_0g = (size_t)HH * HH * sizeof(float)
                         + (size_t)2 * TT * 4 * sizeof(unsigned); // ~67.3 KB
    cudaFuncSetAttribute(k_layer0G, cudaFuncAttributeMaxDynamicSharedMemorySize,
                         (int)smem_0g);
    k_layer0G<<<BB / 2, 256, smem_0g>>>(W1);

    const size_t smem_l1 = (size_t)(32 * HH + HH * OO + 32 + 2 * TT * OO) * sizeof(float)
                         + 2 * TT * 4 * sizeof(unsigned);         // ~45.5 KB
    cudaFuncSetAttribute(k_layer1, cudaFuncAttributeMaxDynamicSharedMemorySize,
                         (int)smem_l1);
    k_layer1<<<BB / 2, 256, smem_l1>>>(V1, Wr, br, out);
}